// round 6
// baseline (speedup 1.0000x reference)
#include <cuda_runtime.h>
#include <cuda_bf16.h>

// LocalLoadBalancingLoss: B=65536, T=792, D=99, L=16.
// loss = mean_b[ var_{ddof=1}(u_b) + 0.5 * max(u_b) ], u = linkTraffic/(cap+1e-8)
//
// Persistent pipelined design: grid=148 (1 block/SM), 1024 threads, 227 KB smem.
// Each block streams ~14 tiles of 32 rows with double-buffered cp.async.
// CSR (tunnels sorted by link) built redundantly per block, held in registers.

#define NUM_T 792
#define NUM_D 99
#define NUM_L 16
#define ROWS 32
#define PST 793                 // odd stride -> conflict-free LDS across rows
#define THREADS 1024
#define GRID 148
#define CSR_STRIDE 128          // per-link slot in global CSR (u16 entries)
#define REG_CHUNKS 16           // 32 register-resident entries per warp
#define REG_ENTRIES (REG_CHUNKS * 2)

#define SP_TILE (ROWS * PST)            // 25376 floats per pred buffer
#define SD_TILE (ROWS * NUM_D)          // 3168 floats per dem buffer
#define SU_OFF  (2 * SP_TILE + 2 * SD_TILE)
#define SMEM_FLOATS (SU_OFF + 1024)     // 58112 floats = 232448 B = 227 KB

__device__ unsigned short g_csr16[NUM_L * CSR_STRIDE + 64];  // zero-init slack
__device__ float g_partials[256];
__device__ unsigned int g_done;

__device__ __forceinline__ void cpa4(unsigned dst, const float* src) {
    asm volatile("cp.async.ca.shared.global [%0], [%1], 4;" :: "r"(dst), "l"(src));
}

__global__ __launch_bounds__(THREADS, 1)
void llb_kernel(const float* __restrict__ pred, const float* __restrict__ dem,
                const int* __restrict__ t2l, const float* __restrict__ cap,
                float* __restrict__ out, int ntiles, float inv_batch) {
    extern __shared__ float smem[];
    float* sp = smem;                    // [2][SP_TILE]
    float* sd = smem + 2 * SP_TILE;      // [2][SD_TILE]
    float* su = smem + SU_OFF;           // scratch: CSR build ints, then u[32][32]

    const int tid  = threadIdx.x;
    const int w    = tid >> 5;
    const int lane = tid & 31;
    const unsigned spA = (unsigned)__cvta_generic_to_shared(sp);
    const unsigned sdA = (unsigned)__cvta_generic_to_shared(sd);

    // ---- prefetch helper: tile t -> buffer q, always commits a group ----
    auto prefetch = [&](int t, int q) {
        if (t < ntiles) {
            const float* gp = pred + (long long)t * (ROWS * NUM_T);
            if (tid < NUM_T) {
                unsigned dst = spA + 4u * (unsigned)(q * SP_TILE + tid);
                const float* s = gp + tid;
                #pragma unroll
                for (int r = 0; r < ROWS; r++)
                    cpa4(dst + 4u * (unsigned)(r * PST), s + r * NUM_T);
            }
            const float* gd = dem + (long long)t * (ROWS * NUM_D);
            #pragma unroll
            for (int i = 0; i < 4; i++) {
                int j = tid + i * THREADS;
                if (j < ROWS * NUM_D)
                    cpa4(sdA + 4u * (unsigned)(q * SD_TILE + j), gd + j);
            }
        }
        asm volatile("cp.async.commit_group;");
    };

    const int t0 = blockIdx.x;
    prefetch(t0, 0);                 // DRAM in flight while we build the CSR
    prefetch(t0 + GRID, 1);

    // ---- CSR build (redundant per block; all blocks write identical data) ----
    int* iw   = (int*)su;            // [25][16] warp counts -> exclusive prefix
    int* itot = iw + 25 * NUM_L;     // [16] per-link totals
    {
        const bool act = (tid < NUM_T);
        int l = 0;
        if (act) l = t2l[tid];
        const int val = act ? l : (64 + lane);   // idle lanes: unique singletons
        if (tid < 25 * NUM_L) iw[tid] = 0;
        __syncthreads();
        unsigned m = __match_any_sync(0xFFFFFFFFu, val);
        int rank = __popc(m & ((1u << lane) - 1u));
        if (act && lane == (__ffs(m) - 1)) iw[w * NUM_L + l] = __popc(m);
        __syncthreads();
        if (tid < NUM_L) {
            int a = 0;
            for (int ww = 0; ww < 25; ww++) {
                int c = iw[ww * NUM_L + tid];
                iw[ww * NUM_L + tid] = a;        // exclusive prefix
                a += c;
            }
            itot[tid] = a;
        }
        __syncthreads();
        if (act) g_csr16[CSR_STRIDE * l + iw[w * NUM_L + l] + rank] = (unsigned short)tid;
        __syncthreads();
    }

    // ---- per-warp segment: warp = link*2 + part; entries preloaded to regs ----
    const int link = w >> 1;
    const int part = w & 1;
    const int len  = itot[link];
    int len0 = (len + 1) >> 1;
    len0 += (len0 & 1);                  // even -> part1 start stays u32-aligned
    if (len0 > len) len0 = len;
    const int myoff = CSR_STRIDE * link + (part ? len0 : 0);
    const int cnt   = part ? (len - len0) : len0;
    const float invc = 1.0f / (cap[link] + 1e-8f);

    unsigned ep[REG_CHUNKS];
    {
        const unsigned* c32 = (const unsigned*)g_csr16 + (myoff >> 1);
        #pragma unroll
        for (int c = 0; c < REG_CHUNKS; c++) ep[c] = c32[c];
    }
    __syncthreads();                     // itot consumed; su becomes u-scratch

    // ---- pipelined tile loop ----
    float acc = 0.0f;
    int t = t0;
    for (int k = 0; t < ntiles; k++, t += GRID) {
        const int p = k & 1;
        asm volatile("cp.async.wait_group 1;");   // tile k resident in buf p
        __syncthreads();

        // phase B: lane = row, each warp walks its half-segment from registers
        const float* pr = sp + p * SP_TILE + lane * PST;
        const float* dr = sd + p * SD_TILE + lane * NUM_D;
        float s0 = 0.f, s1 = 0.f;
        #pragma unroll
        for (int i = 0; i < REG_ENTRIES; i++) {
            if (i >= cnt) break;
            unsigned ch = ep[i >> 1];
            unsigned tt = (i & 1) ? (ch >> 16) : (ch & 0xFFFFu);
            float v = pr[tt] * dr[tt >> 3];
            if (i & 1) s1 += v; else s0 += v;
        }
        for (int i = REG_ENTRIES; i < cnt; i++) {  // rare overflow
            unsigned tt = g_csr16[myoff + i];
            s0 += pr[tt] * dr[tt >> 3];
        }
        su[w * 32 + lane] = (s0 + s1) * invc;      // u[link][part][row]
        __syncthreads();

        // prefetch tile k+2 into buf p (phase-B reads of buf p are done)
        prefetch(t + 2 * GRID, p);

        // stats: warp 0, lane = row (others proceed to next wait/barrier)
        if (w == 0) {
            float sum = 0.f, mx = -1e30f;
            #pragma unroll
            for (int l = 0; l < NUM_L; l++) {
                float x = su[l * 64 + lane] + su[l * 64 + 32 + lane];
                sum += x;
                mx = fmaxf(mx, x);
            }
            const float mean = sum * (1.0f / NUM_L);
            float var = 0.f;
            #pragma unroll
            for (int l = 0; l < NUM_L; l++) {
                float x = su[l * 64 + lane] + su[l * 64 + 32 + lane];
                float d = x - mean;
                var += d * d;
            }
            var *= (1.0f / (NUM_L - 1));           // ddof = 1
            float pv = var + 0.5f * mx;
            #pragma unroll
            for (int o = 16; o > 0; o >>= 1)
                pv += __shfl_down_sync(0xFFFFFFFFu, pv, o);
            if (lane == 0) acc += pv;
        }
        // next-iteration barrier orders warp0's su reads vs. next su writes
    }
    asm volatile("cp.async.wait_all;");

    // ---- fused deterministic reduction: last block sums fixed order ----
    if (tid == 0) g_partials[blockIdx.x] = acc;
    __threadfence();
    int* flag = (int*)su;
    if (tid == 0) {
        unsigned n = atomicAdd(&g_done, 1u);
        flag[0] = (n == GRID - 1) ? 1 : 0;
    }
    __syncthreads();
    if (flag[0] && w == 0) {
        __threadfence();
        float v = 0.f;
        for (int i = lane; i < GRID; i += 32) v += g_partials[i];
        #pragma unroll
        for (int o = 16; o > 0; o >>= 1)
            v += __shfl_down_sync(0xFFFFFFFFu, v, o);
        if (lane == 0) {
            out[0] = v * inv_batch;
            g_done = 0;                 // reset for next graph replay
        }
    }
}

extern "C" void kernel_launch(void* const* d_in, const int* in_sizes, int n_in,
                              void* d_out, int out_size) {
    const float* pred = (const float*)d_in[0];   // [B, 792]
    const float* dem  = (const float*)d_in[1];   // [B, 99]
    const int*   t2l  = (const int*)d_in[2];     // [792]
    const float* cap  = (const float*)d_in[3];   // [16]
    float* out = (float*)d_out;

    const int B = in_sizes[1] / NUM_D;           // 65536
    const int ntiles = B / ROWS;                 // 2048

    static bool attr_set = false;
    const int smem_bytes = SMEM_FLOATS * (int)sizeof(float);   // 232448
    if (!attr_set) {
        cudaFuncSetAttribute(llb_kernel,
                             cudaFuncAttributeMaxDynamicSharedMemorySize, smem_bytes);
        attr_set = true;
    }

    llb_kernel<<<GRID, THREADS, smem_bytes>>>(pred, dem, t2l, cap, out,
                                              ntiles, 1.0f / (float)B);
}

// round 8
// speedup vs baseline: 2.0155x; 2.0155x over previous
#include <cuda_runtime.h>
#include <cuda_bf16.h>

// LocalLoadBalancingLoss: B=65536, T=792, D=99, L=16.
// loss = mean_b[ var_{ddof=1}(u_b) + 0.5 * max(u_b) ], u = linkTraffic/(cap+1e-8)
//
// R7: many small independent blocks. ROWS=16, 512 thr, 57KB smem -> 4 blocks/SM,
// 4096 blocks; cross-block overlap hides cp.async issue + DRAM latency.
// Warp = link, half-warp = CSR-segment half, lane = row. CSR idx via L1-hot LDG.

#define NUM_T 792
#define NUM_D 99
#define NUM_L 16
#define ROWS 16
#define THREADS 512
#define PST 793                 // odd stride -> conflict-free LDS across rows
#define MAX_BLOCKS 4096
#define SETUP_THREADS 800

__device__ unsigned short g_pidx16[NUM_T];  // tunnel ids sorted by link (dest = t>>3)
__device__ int   g_off[NUM_L + 1];
__device__ float g_partials[MAX_BLOCKS];
__device__ unsigned int g_done;

__device__ __forceinline__ void cpa4(unsigned dst, const float* src) {
    asm volatile("cp.async.ca.shared.global [%0], [%1], 4;" :: "r"(dst), "l"(src));
}

// ---------------------------------------------------------------------------
// Setup: link-sorted CSR via __match_any_sync rank + per-link warp prefix.
// ---------------------------------------------------------------------------
__global__ void llb_setup_kernel(const int* __restrict__ t2l) {
    __shared__ int s_wcnt[25][NUM_L];
    __shared__ int s_tot[NUM_L];
    __shared__ int s_off[NUM_L + 1];

    const int tid  = threadIdx.x;       // 800 = 25 warps
    const int w    = tid >> 5;
    const int lane = tid & 31;
    const bool act = (tid < NUM_T);

    if (tid < 25 * NUM_L) ((int*)s_wcnt)[tid] = 0;

    const int l = act ? t2l[tid] : 0;
    const int val = act ? l : (100 + lane);     // idle lanes -> singleton groups
    __syncthreads();

    unsigned m = __match_any_sync(0xFFFFFFFFu, val);
    const int rank = __popc(m & ((1u << lane) - 1u));
    if (act && lane == (__ffs(m) - 1)) s_wcnt[w][l] = __popc(m);
    __syncthreads();

    if (tid < NUM_L) {
        int acc = 0;
        for (int ww = 0; ww < 25; ww++) {
            int c = s_wcnt[ww][tid];
            s_wcnt[ww][tid] = acc;               // exclusive prefix over warps
            acc += c;
        }
        s_tot[tid] = acc;
    }
    __syncthreads();

    if (tid == 0) {
        int a = 0;
        for (int ll = 0; ll < NUM_L; ll++) { s_off[ll] = a; a += s_tot[ll]; }
        s_off[NUM_L] = a;                        // == 792
    }
    __syncthreads();

    if (act) g_pidx16[s_off[l] + s_wcnt[w][l] + rank] = (unsigned short)tid;
    if (tid <= NUM_L) g_off[tid] = s_off[tid];
}

// ---------------------------------------------------------------------------
// Main: 4096 blocks x 16 rows. cp.async stage-in; warp=link, half-warp=segment
// half, lane=row; fused deterministic final reduction.
// ---------------------------------------------------------------------------
__global__ __launch_bounds__(THREADS, 4)
void llb_main_kernel(const float* __restrict__ pred,
                     const float* __restrict__ dem,
                     const float* __restrict__ cap,
                     float* __restrict__ out,
                     int ntiles, float inv_batch) {
    extern __shared__ float smem[];
    float* sp = smem;                    // [16][793]
    float* sd = smem + ROWS * PST;       // [16][99]; later overlaid as su[16][17]
    __shared__ int sflag;

    const int tid  = threadIdx.x;
    const int w    = tid >> 5;           // link
    const int lane = tid & 31;
    const int part = lane >> 4;          // segment half
    const int r    = lane & 15;          // row

    // metadata early (L2 latency overlaps staging)
    const int   beg  = g_off[w];
    const int   end  = g_off[w + 1];
    const float invc = 1.0f / (cap[w] + 1e-8f);
    const int   len  = end - beg;
    const int   len0 = (len + 1) >> 1;
    const int   mybeg = beg + (part ? len0 : 0);
    const int   mycnt = part ? (len - len0) : len0;

    const long long tile = blockIdx.x;
    const float* gp = pred + tile * (ROWS * NUM_T);
    const float* gd = dem  + tile * (ROWS * NUM_D);
    const unsigned spA = (unsigned)__cvta_generic_to_shared(sp);
    const unsigned sdA = (unsigned)__cvta_generic_to_shared(sd);

    // ---- stage-in ----
    #pragma unroll
    for (int k = 0; k < 25; k++) {
        int i = tid + k * THREADS;
        if (i < ROWS * NUM_T) {
            int rr = (unsigned)i / NUM_T;        // smem idx = i + rr (stride 793)
            cpa4(spA + 4u * (unsigned)(i + rr), gp + i);
        }
    }
    #pragma unroll
    for (int k = 0; k < 4; k++) {
        int i = tid + k * THREADS;
        if (i < ROWS * NUM_D) cpa4(sdA + 4u * (unsigned)i, gd + i);
    }
    asm volatile("cp.async.commit_group;");
    asm volatile("cp.async.wait_group 0;");
    __syncthreads();

    // ---- phase B: half-warp walks its half-segment, lane = row ----
    const float* pr = sp + r * PST;
    const float* dm = sd + r * NUM_D;
    const unsigned short* ix = g_pidx16 + mybeg;

    float s0 = 0.f, s1 = 0.f;
    int i = 0;
    for (; i + 1 < mycnt; i += 2) {
        int t0 = __ldg(ix + i);
        int t1 = __ldg(ix + i + 1);
        s0 += pr[t0] * dm[t0 >> 3];
        s1 += pr[t1] * dm[t1 >> 3];
    }
    if (i < mycnt) {
        int t0 = __ldg(ix + i);
        s0 += pr[t0] * dm[t0 >> 3];
    }
    float u = (s0 + s1) * invc;
    u += __shfl_down_sync(0xFFFFFFFFu, u, 16);   // combine segment halves

    __syncthreads();                     // all sd reads done -> overlay su
    float* su = sd;                      // [16 links][17]
    if (part == 0) su[w * 17 + r] = u;
    __syncthreads();

    // ---- per-row stats: warp 0, lanes 0-15 (row = lane) ----
    float blocksum = 0.f;
    if (w == 0 && part == 0) {
        float sum = 0.f, mx = -1e30f;
        #pragma unroll
        for (int l = 0; l < NUM_L; l++) {
            float x = su[l * 17 + r];
            sum += x;
            mx = fmaxf(mx, x);
        }
        const float mean = sum * (1.0f / NUM_L);
        float var = 0.f;
        #pragma unroll
        for (int l = 0; l < NUM_L; l++) {
            float d = su[l * 17 + r] - mean;
            var += d * d;
        }
        var *= (1.0f / (NUM_L - 1));             // ddof = 1
        float pv = var + 0.5f * mx;
        #pragma unroll
        for (int o = 8; o > 0; o >>= 1)
            pv += __shfl_down_sync(0x0000FFFFu, pv, o);
        blocksum = pv;
    }
    if (tid == 0) g_partials[blockIdx.x] = blocksum;

    // ---- fused deterministic reduction: last block, fixed-order tree ----
    __threadfence();
    if (tid == 0) {
        unsigned n = atomicAdd(&g_done, 1u);
        sflag = (n == (unsigned)(gridDim.x - 1)) ? 1 : 0;
    }
    __syncthreads();
    if (sflag) {
        __threadfence();
        float v = 0.f;
        #pragma unroll
        for (int k = 0; k < MAX_BLOCKS / THREADS; k++)
            v += g_partials[tid + k * THREADS];  // fixed order per thread
        float* rb = sp;                          // reuse smem
        rb[tid] = v;
        __syncthreads();
        #pragma unroll
        for (int s = THREADS / 2; s > 0; s >>= 1) {
            if (tid < s) rb[tid] += rb[tid + s]; // fixed pairing -> deterministic
            __syncthreads();
        }
        if (tid == 0) {
            out[0] = rb[0] * inv_batch;
            g_done = 0;                          // reset for next graph replay
        }
    }
}

extern "C" void kernel_launch(void* const* d_in, const int* in_sizes, int n_in,
                              void* d_out, int out_size) {
    const float* pred = (const float*)d_in[0];   // [B, 792]
    const float* dem  = (const float*)d_in[1];   // [B, 99]
    const int*   t2l  = (const int*)d_in[2];     // [792]
    const float* cap  = (const float*)d_in[3];   // [16]
    float* out = (float*)d_out;

    const int B = in_sizes[1] / NUM_D;           // 65536
    const int ntiles = B / ROWS;                 // 4096

    static bool attr_set = false;
    const int smem_bytes = (ROWS * PST + ROWS * NUM_D) * (int)sizeof(float); // 57088
    if (!attr_set) {
        cudaFuncSetAttribute(llb_main_kernel,
                             cudaFuncAttributeMaxDynamicSharedMemorySize, smem_bytes);
        attr_set = true;
    }

    llb_setup_kernel<<<1, SETUP_THREADS>>>(t2l);
    llb_main_kernel<<<ntiles, THREADS, smem_bytes>>>(pred, dem, cap, out,
                                                     ntiles, 1.0f / (float)B);
}